// round 1
// baseline (speedup 1.0000x reference)
#include <cuda_runtime.h>
#include <math.h>

// ---------------- problem constants ----------------
#define B_SZ   4
#define SEQ    2048
#define DMODEL 1024
#define NSTATE 16
#define MROWS  (B_SZ * SEQ)        // 8192

// chunked scan config
#define NC     32                  // number of chunks
#define CHUNK  (SEQ / NC)          // 64 steps per chunk

// ---------------- scratch (static __device__, no allocations) ----------------
__device__ float g_delta[MROWS * DMODEL];          // 32 MB
__device__ float g_Bm[MROWS * NSTATE];
__device__ float g_Cm[MROWS * NSTATE];
__device__ float g_hfin [B_SZ * NC * NSTATE * DMODEL];   // 8 MB, layout [b][c][n][d]
__device__ float g_hinit[B_SZ * NC * NSTATE * DMODEL];   // 8 MB, layout [b][c][n][d]
__device__ float g_dtsum[B_SZ * NC * DMODEL];

__device__ __forceinline__ float softplus_f(float z) {
    return (z > 20.0f) ? z : log1pf(expf(z));
}

// ---------------- Kernel 1: delta GEMM (8192x1024 = x @ Wd + bd, softplus) ----
// 128x128 tile, BK=16, 256 threads, 8x8 per thread. fp32 SIMT.
#define BM 128
#define BN 128
#define BK 16
#define TM 8
#define TN 8

__global__ __launch_bounds__(256, 2)
void gemm_delta_kernel(const float* __restrict__ X,
                       const float* __restrict__ W,
                       const float* __restrict__ bias) {
    __shared__ float As[BK][BM];
    __shared__ float Bs[BK][BN];

    const int bm = blockIdx.y * BM;
    const int bn = blockIdx.x * BN;
    const int tid = threadIdx.x;
    const int tx = tid & 15;       // 0..15  (col group)
    const int ty = tid >> 4;       // 0..15  (row group)

    float acc[TM][TN];
    #pragma unroll
    for (int i = 0; i < TM; i++)
        #pragma unroll
        for (int j = 0; j < TN; j++) acc[i][j] = 0.0f;

    for (int k0 = 0; k0 < DMODEL; k0 += BK) {
        // load A tile: 128 rows x 16 k  (512 float4s, 2 per thread)
        #pragma unroll
        for (int i = 0; i < 2; i++) {
            int idx  = tid + i * 256;
            int row  = idx >> 2;
            int kk   = (idx & 3) * 4;
            float4 v = *(const float4*)&X[(bm + row) * DMODEL + k0 + kk];
            As[kk + 0][row] = v.x;
            As[kk + 1][row] = v.y;
            As[kk + 2][row] = v.z;
            As[kk + 3][row] = v.w;
            // load B tile: 16 k-rows x 128 cols
            int brow = idx >> 5;          // 0..15
            int bcol = (idx & 31) * 4;    // 0..124
            float4 w = *(const float4*)&W[(k0 + brow) * DMODEL + bn + bcol];
            *(float4*)&Bs[brow][bcol] = w;
        }
        __syncthreads();

        #pragma unroll
        for (int k = 0; k < BK; k++) {
            float a[TM], b[TN];
            float4 a0 = *(const float4*)&As[k][ty * TM + 0];
            float4 a1 = *(const float4*)&As[k][ty * TM + 4];
            a[0]=a0.x; a[1]=a0.y; a[2]=a0.z; a[3]=a0.w;
            a[4]=a1.x; a[5]=a1.y; a[6]=a1.z; a[7]=a1.w;
            float4 b0 = *(const float4*)&Bs[k][tx * TN + 0];
            float4 b1 = *(const float4*)&Bs[k][tx * TN + 4];
            b[0]=b0.x; b[1]=b0.y; b[2]=b0.z; b[3]=b0.w;
            b[4]=b1.x; b[5]=b1.y; b[6]=b1.z; b[7]=b1.w;
            #pragma unroll
            for (int i = 0; i < TM; i++)
                #pragma unroll
                for (int j = 0; j < TN; j++)
                    acc[i][j] += a[i] * b[j];
        }
        __syncthreads();
    }

    // epilogue: + bias, softplus, store (float4)
    float bv[TN];
    #pragma unroll
    for (int j = 0; j < TN; j++) bv[j] = bias[bn + tx * TN + j];

    #pragma unroll
    for (int i = 0; i < TM; i++) {
        int row = bm + ty * TM + i;
        #pragma unroll
        for (int j = 0; j < TN; j += 4) {
            int col = bn + tx * TN + j;
            float4 v;
            v.x = softplus_f(acc[i][j + 0] + bv[j + 0]);
            v.y = softplus_f(acc[i][j + 1] + bv[j + 1]);
            v.z = softplus_f(acc[i][j + 2] + bv[j + 2]);
            v.w = softplus_f(acc[i][j + 3] + bv[j + 3]);
            *(float4*)&g_delta[row * DMODEL + col] = v;
        }
    }
}

// ---------------- Kernel 2: Bm/Cm projections (8192 x 16 each) ---------------
// One warp handles 4 rows; lanes 0-15 compute Bm cols, lanes 16-31 Cm cols.
__global__ __launch_bounds__(256)
void proj_bc_kernel(const float* __restrict__ x,
                    const float* __restrict__ Wb, const float* __restrict__ bb,
                    const float* __restrict__ Wc, const float* __restrict__ bc) {
    const int warp = threadIdx.x >> 5;
    const int lane = threadIdx.x & 31;
    const int row0 = (blockIdx.x * 8 + warp) * 4;   // grid.x = 256 -> rows 0..8191
    const int j = lane & 15;
    const bool isC = lane >= 16;
    const float* __restrict__ W = isC ? Wc : Wb;

    float acc0 = 0.f, acc1 = 0.f, acc2 = 0.f, acc3 = 0.f;
    for (int k0 = 0; k0 < DMODEL; k0 += 32) {
        float x0 = x[(row0 + 0) * DMODEL + k0 + lane];
        float x1 = x[(row0 + 1) * DMODEL + k0 + lane];
        float x2 = x[(row0 + 2) * DMODEL + k0 + lane];
        float x3 = x[(row0 + 3) * DMODEL + k0 + lane];
        #pragma unroll
        for (int kk = 0; kk < 32; kk++) {
            float w = W[(k0 + kk) * NSTATE + j];
            acc0 = fmaf(__shfl_sync(0xffffffffu, x0, kk), w, acc0);
            acc1 = fmaf(__shfl_sync(0xffffffffu, x1, kk), w, acc1);
            acc2 = fmaf(__shfl_sync(0xffffffffu, x2, kk), w, acc2);
            acc3 = fmaf(__shfl_sync(0xffffffffu, x3, kk), w, acc3);
        }
    }
    float bias = isC ? bc[j] : bb[j];
    float* out = isC ? g_Cm : g_Bm;
    out[(row0 + 0) * NSTATE + j] = acc0 + bias;
    out[(row0 + 1) * NSTATE + j] = acc1 + bias;
    out[(row0 + 2) * NSTATE + j] = acc2 + bias;
    out[(row0 + 3) * NSTATE + j] = acc3 + bias;
}

// ---------------- Kernel 3: scan pass 1 (local chunk scans, h0 = 0) ----------
// grid: (DMODEL/256, NC, B). thread = one d channel; 16 states in registers.
__global__ __launch_bounds__(256)
void scan_pass1_kernel(const float* __restrict__ x,
                       const float* __restrict__ A_log) {
    const int d = blockIdx.x * 256 + threadIdx.x;
    const int c = blockIdx.y;
    const int b = blockIdx.z;
    const int t0 = c * CHUNK;

    __shared__ float sB[CHUNK * NSTATE];
    for (int i = threadIdx.x; i < CHUNK * NSTATE; i += 256)
        sB[i] = g_Bm[(b * SEQ + t0) * NSTATE + i];
    __syncthreads();

    float A[NSTATE];
    #pragma unroll
    for (int n = 0; n < NSTATE; n++)
        A[n] = -__expf(A_log[d * NSTATE + n]);

    float h[NSTATE];
    #pragma unroll
    for (int n = 0; n < NSTATE; n++) h[n] = 0.0f;
    float dts = 0.0f;

    const float* __restrict__ xp = x       + (size_t)(b * SEQ + t0) * DMODEL + d;
    const float* __restrict__ dp = g_delta + (size_t)(b * SEQ + t0) * DMODEL + d;

    for (int t = 0; t < CHUNK; t++) {
        float xv = xp[t * DMODEL];
        float dt = dp[t * DMODEL];
        dts += dt;
        float dtx = dt * xv;
        #pragma unroll
        for (int n = 0; n < NSTATE; n++) {
            float ab = __expf(dt * A[n]);
            h[n] = fmaf(ab, h[n], dtx * sB[t * NSTATE + n]);
        }
    }

    const int base = ((b * NC + c) * NSTATE) * DMODEL + d;
    #pragma unroll
    for (int n = 0; n < NSTATE; n++)
        g_hfin[base + n * DMODEL] = h[n];
    g_dtsum[(b * NC + c) * DMODEL + d] = dts;
}

// ---------------- Kernel 4: sequential chunk combine (tiny) ------------------
// thread = one (b,d); walks 32 chunks: h_in[c+1] = exp(A*dtsum_c)*h_in[c] + hfin_c
__global__ __launch_bounds__(256)
void combine_kernel(const float* __restrict__ A_log) {
    const int idx = blockIdx.x * 256 + threadIdx.x;   // 0..B*D-1
    const int b = idx / DMODEL;
    const int d = idx % DMODEL;

    float A[NSTATE];
    #pragma unroll
    for (int n = 0; n < NSTATE; n++)
        A[n] = -__expf(A_log[d * NSTATE + n]);

    float h[NSTATE];
    #pragma unroll
    for (int n = 0; n < NSTATE; n++) h[n] = 0.0f;

    for (int c = 0; c < NC; c++) {
        const int base = ((b * NC + c) * NSTATE) * DMODEL + d;
        #pragma unroll
        for (int n = 0; n < NSTATE; n++)
            g_hinit[base + n * DMODEL] = h[n];
        float dts = g_dtsum[(b * NC + c) * DMODEL + d];
        #pragma unroll
        for (int n = 0; n < NSTATE; n++)
            h[n] = fmaf(__expf(dts * A[n]), h[n], g_hfin[base + n * DMODEL]);
    }
}

// ---------------- Kernel 5: scan pass 2 (replay with real h_init, emit y) ----
__global__ __launch_bounds__(256)
void scan_pass2_kernel(const float* __restrict__ x,
                       const float* __restrict__ A_log,
                       const float* __restrict__ D_skip,
                       float* __restrict__ y) {
    const int d = blockIdx.x * 256 + threadIdx.x;
    const int c = blockIdx.y;
    const int b = blockIdx.z;
    const int t0 = c * CHUNK;

    __shared__ float sB[CHUNK * NSTATE];
    __shared__ float sC[CHUNK * NSTATE];
    for (int i = threadIdx.x; i < CHUNK * NSTATE; i += 256) {
        sB[i] = g_Bm[(b * SEQ + t0) * NSTATE + i];
        sC[i] = g_Cm[(b * SEQ + t0) * NSTATE + i];
    }
    __syncthreads();

    float A[NSTATE];
    #pragma unroll
    for (int n = 0; n < NSTATE; n++)
        A[n] = -__expf(A_log[d * NSTATE + n]);

    float h[NSTATE];
    const int base = ((b * NC + c) * NSTATE) * DMODEL + d;
    #pragma unroll
    for (int n = 0; n < NSTATE; n++)
        h[n] = g_hinit[base + n * DMODEL];

    const float dsk = D_skip[d];
    const float* __restrict__ xp = x       + (size_t)(b * SEQ + t0) * DMODEL + d;
    const float* __restrict__ dp = g_delta + (size_t)(b * SEQ + t0) * DMODEL + d;
    float* __restrict__ yp       = y       + (size_t)(b * SEQ + t0) * DMODEL + d;

    for (int t = 0; t < CHUNK; t++) {
        float xv = xp[t * DMODEL];
        float dt = dp[t * DMODEL];
        float dtx = dt * xv;
        float acc = xv * dsk;
        #pragma unroll
        for (int n = 0; n < NSTATE; n++) {
            float ab = __expf(dt * A[n]);
            h[n] = fmaf(ab, h[n], dtx * sB[t * NSTATE + n]);
            acc = fmaf(h[n], sC[t * NSTATE + n], acc);
        }
        yp[t * DMODEL] = acc;
    }
}

// ---------------- launch ----------------
extern "C" void kernel_launch(void* const* d_in, const int* in_sizes, int n_in,
                              void* d_out, int out_size) {
    const float* x      = (const float*)d_in[0];
    const float* A_log  = (const float*)d_in[1];
    const float* D_skip = (const float*)d_in[2];
    const float* Wd     = (const float*)d_in[3];
    const float* bd     = (const float*)d_in[4];
    const float* Wb     = (const float*)d_in[5];
    const float* bb     = (const float*)d_in[6];
    const float* Wc     = (const float*)d_in[7];
    const float* bc     = (const float*)d_in[8];
    float* y = (float*)d_out;

    // 1) delta = softplus(x @ Wd + bd)
    dim3 ggrid(DMODEL / BN, MROWS / BM);          // (8, 64)
    gemm_delta_kernel<<<ggrid, 256>>>(x, Wd, bd);

    // 2) Bm, Cm projections
    proj_bc_kernel<<<MROWS / 32, 256>>>(x, Wb, bb, Wc, bc);

    // 3) chunked parallel scan
    dim3 sgrid(DMODEL / 256, NC, B_SZ);           // (4, 32, 4) = 512 blocks
    scan_pass1_kernel<<<sgrid, 256>>>(x, A_log);
    combine_kernel<<<(B_SZ * DMODEL) / 256, 256>>>(A_log);
    scan_pass2_kernel<<<sgrid, 256>>>(x, A_log, D_skip, y);
}

// round 2
// speedup vs baseline: 1.8925x; 1.8925x over previous
#include <cuda_runtime.h>
#include <math.h>
#include <stdint.h>

// ---------------- problem constants ----------------
#define B_SZ   4
#define SEQ    2048
#define DMODEL 1024
#define NSTATE 16
#define MROWS  (B_SZ * SEQ)        // 8192

// chunked scan config
#define NC     32
#define CHUNK  (SEQ / NC)          // 64

// ---------------- scratch ----------------
__device__ float g_delta[MROWS * DMODEL];
__device__ float g_Bm[MROWS * NSTATE];
__device__ float g_Cm[MROWS * NSTATE];
__device__ float g_hfin [B_SZ * NC * NSTATE * DMODEL];   // [b][c][n][d]
__device__ float g_hinit[B_SZ * NC * NSTATE * DMODEL];
__device__ float g_dtsum[B_SZ * NC * DMODEL];

__device__ __forceinline__ float softplus_f(float z) {
    return (z > 20.0f) ? z : log1pf(expf(z));
}

// ---------------- TF32 tensor-core GEMM: delta = softplus(x @ Wd + bd) -------
// M=8192, N=1024, K=1024. BM=128, BN=128, BK=16, 256 threads (8 warps 4x2),
// warp tile 32x64, mma.sync.m16n8k8.tf32, cp.async double-buffered smem.
#define BM 128
#define BN 128
#define BKT 16
#define ASTR 20      // A smem row stride (floats): (20*g + t) % 32 all-distinct
#define BSTR 136     // B smem row stride (floats): (136*t + g) % 32 all-distinct

__device__ __forceinline__ void cp_async16(void* smem, const void* gmem) {
    uint32_t s = (uint32_t)__cvta_generic_to_shared(smem);
    asm volatile("cp.async.cg.shared.global [%0], [%1], 16;\n" :: "r"(s), "l"(gmem));
}
__device__ __forceinline__ uint32_t to_tf32(float f) {
    uint32_t u;
    asm volatile("cvt.rna.tf32.f32 %0, %1;\n" : "=r"(u) : "f"(f));
    return u;
}

__global__ __launch_bounds__(256, 2)
void gemm_delta_tf32_kernel(const float* __restrict__ X,
                            const float* __restrict__ W,
                            const float* __restrict__ bias) {
    __shared__ float As[2][BM * ASTR];   // 10240 B each
    __shared__ float Bs[2][BKT * BSTR];  //  8704 B each

    const int bm = blockIdx.y * BM;
    const int bn = blockIdx.x * BN;
    const int tid = threadIdx.x;
    const int lane = tid & 31;
    const int w = tid >> 5;
    const int g = lane >> 2;          // 0..7
    const int t = lane & 3;           // 0..3
    const int warpM = w >> 1;         // 0..3
    const int warpN = w & 1;          // 0..1
    const int mrow0 = warpM * 32;
    const int ncol0 = warpN * 64;

    // per-tile load indices (2 A float4s + 2 B float4s per thread)
    const int arow0 = tid >> 1;                 // 0..127 (idx = tid)
    const int akk0  = (tid & 1) * 8;            // hmm: need (idx&3)*4 mapping
    // use explicit mapping: idx in [0,512): row=idx>>2, kk=(idx&3)*4
    float acc[2][8][4];
    #pragma unroll
    for (int i = 0; i < 2; i++)
        #pragma unroll
        for (int j = 0; j < 8; j++)
            #pragma unroll
            for (int q = 0; q < 4; q++) acc[i][j][q] = 0.0f;

    const int NIT = DMODEL / BKT;    // 64

    // tile-load lambda (issues cp.async for tile 'it' into buffer 'buf')
    auto issue_tile = [&](int it, int buf) {
        int k0 = it * BKT;
        #pragma unroll
        for (int i = 0; i < 2; i++) {
            int idx = tid + i * 256;             // 0..511
            int row = idx >> 2;                  // 0..127
            int kk  = (idx & 3) * 4;             // 0,4,8,12
            cp_async16(&As[buf][row * ASTR + kk],
                       &X[(size_t)(bm + row) * DMODEL + k0 + kk]);
            int krow = idx >> 5;                 // 0..15
            int col  = (idx & 31) * 4;           // 0..124
            cp_async16(&Bs[buf][krow * BSTR + col],
                       &W[(size_t)(k0 + krow) * DMODEL + bn + col]);
        }
        asm volatile("cp.async.commit_group;\n");
    };

    issue_tile(0, 0);

    for (int it = 0; it < NIT; it++) {
        const int p = it & 1;
        if (it + 1 < NIT) issue_tile(it + 1, p ^ 1);
        if (it + 1 < NIT) { asm volatile("cp.async.wait_group 1;\n"); }
        else              { asm volatile("cp.async.wait_group 0;\n"); }
        __syncthreads();

        #pragma unroll
        for (int ks = 0; ks < 2; ks++) {
            const int k = ks * 8;
            uint32_t af[2][4];
            #pragma unroll
            for (int mt = 0; mt < 2; mt++) {
                int r0 = mrow0 + mt * 16;
                af[mt][0] = to_tf32(As[p][(r0 + g)     * ASTR + k + t]);
                af[mt][1] = to_tf32(As[p][(r0 + 8 + g) * ASTR + k + t]);
                af[mt][2] = to_tf32(As[p][(r0 + g)     * ASTR + k + t + 4]);
                af[mt][3] = to_tf32(As[p][(r0 + 8 + g) * ASTR + k + t + 4]);
            }
            uint32_t bf[8][2];
            #pragma unroll
            for (int nt = 0; nt < 8; nt++) {
                int c0 = ncol0 + nt * 8 + g;
                bf[nt][0] = to_tf32(Bs[p][(k + t)     * BSTR + c0]);
                bf[nt][1] = to_tf32(Bs[p][(k + t + 4) * BSTR + c0]);
            }
            #pragma unroll
            for (int mt = 0; mt < 2; mt++)
                #pragma unroll
                for (int nt = 0; nt < 8; nt++) {
                    asm volatile(
                        "mma.sync.aligned.m16n8k8.row.col.f32.tf32.tf32.f32 "
                        "{%0,%1,%2,%3}, {%4,%5,%6,%7}, {%8,%9}, {%0,%1,%2,%3};\n"
                        : "+f"(acc[mt][nt][0]), "+f"(acc[mt][nt][1]),
                          "+f"(acc[mt][nt][2]), "+f"(acc[mt][nt][3])
                        : "r"(af[mt][0]), "r"(af[mt][1]), "r"(af[mt][2]), "r"(af[mt][3]),
                          "r"(bf[nt][0]), "r"(bf[nt][1]));
                }
        }
        __syncthreads();
    }

    // epilogue: +bias, softplus, store float2 pairs
    #pragma unroll
    for (int nt = 0; nt < 8; nt++) {
        int col = bn + ncol0 + nt * 8 + 2 * t;
        float b0 = bias[col];
        float b1 = bias[col + 1];
        #pragma unroll
        for (int mt = 0; mt < 2; mt++) {
            int r0 = bm + mrow0 + mt * 16 + g;
            float2 v0, v1;
            v0.x = softplus_f(acc[mt][nt][0] + b0);
            v0.y = softplus_f(acc[mt][nt][1] + b1);
            v1.x = softplus_f(acc[mt][nt][2] + b0);
            v1.y = softplus_f(acc[mt][nt][3] + b1);
            *(float2*)&g_delta[(size_t)r0 * DMODEL + col] = v0;
            *(float2*)&g_delta[(size_t)(r0 + 8) * DMODEL + col] = v1;
        }
    }
}

// ---------------- Kernel 2: Bm/Cm projections --------------------------------
__global__ __launch_bounds__(256)
void proj_bc_kernel(const float* __restrict__ x,
                    const float* __restrict__ Wb, const float* __restrict__ bb,
                    const float* __restrict__ Wc, const float* __restrict__ bc) {
    const int warp = threadIdx.x >> 5;
    const int lane = threadIdx.x & 31;
    const int row0 = (blockIdx.x * 8 + warp) * 4;
    const int j = lane & 15;
    const bool isC = lane >= 16;
    const float* __restrict__ W = isC ? Wc : Wb;

    float acc0 = 0.f, acc1 = 0.f, acc2 = 0.f, acc3 = 0.f;
    for (int k0 = 0; k0 < DMODEL; k0 += 32) {
        float x0 = x[(row0 + 0) * DMODEL + k0 + lane];
        float x1 = x[(row0 + 1) * DMODEL + k0 + lane];
        float x2 = x[(row0 + 2) * DMODEL + k0 + lane];
        float x3 = x[(row0 + 3) * DMODEL + k0 + lane];
        #pragma unroll
        for (int kk = 0; kk < 32; kk++) {
            float w = W[(k0 + kk) * NSTATE + j];
            acc0 = fmaf(__shfl_sync(0xffffffffu, x0, kk), w, acc0);
            acc1 = fmaf(__shfl_sync(0xffffffffu, x1, kk), w, acc1);
            acc2 = fmaf(__shfl_sync(0xffffffffu, x2, kk), w, acc2);
            acc3 = fmaf(__shfl_sync(0xffffffffu, x3, kk), w, acc3);
        }
    }
    float bias = isC ? bc[j] : bb[j];
    float* out = isC ? g_Cm : g_Bm;
    out[(row0 + 0) * NSTATE + j] = acc0 + bias;
    out[(row0 + 1) * NSTATE + j] = acc1 + bias;
    out[(row0 + 2) * NSTATE + j] = acc2 + bias;
    out[(row0 + 3) * NSTATE + j] = acc3 + bias;
}

// ---------------- Kernel 3: scan pass 1 --------------------------------------
__global__ __launch_bounds__(256)
void scan_pass1_kernel(const float* __restrict__ x,
                       const float* __restrict__ A_log) {
    const int d = blockIdx.x * 256 + threadIdx.x;
    const int c = blockIdx.y;
    const int b = blockIdx.z;
    const int t0 = c * CHUNK;

    __shared__ float sB[CHUNK * NSTATE];
    for (int i = threadIdx.x; i < CHUNK * NSTATE; i += 256)
        sB[i] = g_Bm[(b * SEQ + t0) * NSTATE + i];
    __syncthreads();

    float A[NSTATE];
    #pragma unroll
    for (int n = 0; n < NSTATE; n++)
        A[n] = -__expf(A_log[d * NSTATE + n]);

    float h[NSTATE];
    #pragma unroll
    for (int n = 0; n < NSTATE; n++) h[n] = 0.0f;
    float dts = 0.0f;

    const float* __restrict__ xp = x       + (size_t)(b * SEQ + t0) * DMODEL + d;
    const float* __restrict__ dp = g_delta + (size_t)(b * SEQ + t0) * DMODEL + d;

    #pragma unroll 2
    for (int t = 0; t < CHUNK; t++) {
        float xv = xp[t * DMODEL];
        float dt = dp[t * DMODEL];
        dts += dt;
        float dtx = dt * xv;
        #pragma unroll
        for (int n = 0; n < NSTATE; n++) {
            float ab = __expf(dt * A[n]);
            h[n] = fmaf(ab, h[n], dtx * sB[t * NSTATE + n]);
        }
    }

    const int base = ((b * NC + c) * NSTATE) * DMODEL + d;
    #pragma unroll
    for (int n = 0; n < NSTATE; n++)
        g_hfin[base + n * DMODEL] = h[n];
    g_dtsum[(b * NC + c) * DMODEL + d] = dts;
}

// ---------------- Kernel 4: chunk combine (parallel over b,n,d) --------------
// grid (DMODEL/256, NSTATE, B); thread = one (b,n,d) scalar chain over 32 chunks
__global__ __launch_bounds__(256)
void combine_kernel(const float* __restrict__ A_log) {
    const int d = blockIdx.x * 256 + threadIdx.x;
    const int n = blockIdx.y;
    const int b = blockIdx.z;

    const float A = -__expf(A_log[d * NSTATE + n]);
    float h = 0.0f;

    #pragma unroll 4
    for (int c = 0; c < NC; c++) {
        const int base = ((b * NC + c) * NSTATE + n) * DMODEL + d;
        g_hinit[base] = h;
        float dts = g_dtsum[(b * NC + c) * DMODEL + d];
        h = fmaf(__expf(dts * A), h, g_hfin[base]);
    }
}

// ---------------- Kernel 5: scan pass 2 --------------------------------------
__global__ __launch_bounds__(256)
void scan_pass2_kernel(const float* __restrict__ x,
                       const float* __restrict__ A_log,
                       const float* __restrict__ D_skip,
                       float* __restrict__ y) {
    const int d = blockIdx.x * 256 + threadIdx.x;
    const int c = blockIdx.y;
    const int b = blockIdx.z;
    const int t0 = c * CHUNK;

    __shared__ float sB[CHUNK * NSTATE];
    __shared__ float sC[CHUNK * NSTATE];
    for (int i = threadIdx.x; i < CHUNK * NSTATE; i += 256) {
        sB[i] = g_Bm[(b * SEQ + t0) * NSTATE + i];
        sC[i] = g_Cm[(b * SEQ + t0) * NSTATE + i];
    }
    __syncthreads();

    float A[NSTATE];
    #pragma unroll
    for (int n = 0; n < NSTATE; n++)
        A[n] = -__expf(A_log[d * NSTATE + n]);

    float h[NSTATE];
    const int base = ((b * NC + c) * NSTATE) * DMODEL + d;
    #pragma unroll
    for (int n = 0; n < NSTATE; n++)
        h[n] = g_hinit[base + n * DMODEL];

    const float dsk = D_skip[d];
    const float* __restrict__ xp = x       + (size_t)(b * SEQ + t0) * DMODEL + d;
    const float* __restrict__ dp = g_delta + (size_t)(b * SEQ + t0) * DMODEL + d;
    float* __restrict__ yp       = y       + (size_t)(b * SEQ + t0) * DMODEL + d;

    #pragma unroll 2
    for (int t = 0; t < CHUNK; t++) {
        float xv = xp[t * DMODEL];
        float dt = dp[t * DMODEL];
        float dtx = dt * xv;
        float acc = xv * dsk;
        #pragma unroll
        for (int n = 0; n < NSTATE; n++) {
            float ab = __expf(dt * A[n]);
            h[n] = fmaf(ab, h[n], dtx * sB[t * NSTATE + n]);
            acc = fmaf(h[n], sC[t * NSTATE + n], acc);
        }
        yp[t * DMODEL] = acc;
    }
}

// ---------------- launch ----------------
extern "C" void kernel_launch(void* const* d_in, const int* in_sizes, int n_in,
                              void* d_out, int out_size) {
    const float* x      = (const float*)d_in[0];
    const float* A_log  = (const float*)d_in[1];
    const float* D_skip = (const float*)d_in[2];
    const float* Wd     = (const float*)d_in[3];
    const float* bd     = (const float*)d_in[4];
    const float* Wb     = (const float*)d_in[5];
    const float* bb     = (const float*)d_in[6];
    const float* Wc     = (const float*)d_in[7];
    const float* bc     = (const float*)d_in[8];
    float* y = (float*)d_out;

    // 1) delta = softplus(x @ Wd + bd) — TF32 tensor cores
    dim3 ggrid(DMODEL / BN, MROWS / BM);          // (8, 64)
    gemm_delta_tf32_kernel<<<ggrid, 256>>>(x, Wd, bd);

    // 2) Bm, Cm projections
    proj_bc_kernel<<<MROWS / 32, 256>>>(x, Wb, bb, Wc, bc);

    // 3) chunked parallel scan
    dim3 sgrid(DMODEL / 256, NC, B_SZ);           // 512 blocks
    scan_pass1_kernel<<<sgrid, 256>>>(x, A_log);
    dim3 cgrid(DMODEL / 256, NSTATE, B_SZ);       // 256 blocks, 65536 threads
    combine_kernel<<<cgrid, 256>>>(A_log);
    scan_pass2_kernel<<<sgrid, 256>>>(x, A_log, D_skip, y);
}

// round 3
// speedup vs baseline: 2.0583x; 1.0876x over previous
#include <cuda_runtime.h>
#include <math.h>
#include <stdint.h>

// ---------------- problem constants ----------------
#define B_SZ   4
#define SEQ    2048
#define DMODEL 1024
#define NSTATE 16
#define MROWS  (B_SZ * SEQ)        // 8192

// chunked scan config
#define NC     64
#define CHUNK  (SEQ / NC)          // 32

// ---------------- scratch ----------------
__device__ float g_delta[MROWS * DMODEL];
__device__ float g_Bm[MROWS * NSTATE];
__device__ float g_Cm[MROWS * NSTATE];
__device__ float g_hfin [B_SZ * NC * NSTATE * DMODEL];   // [b][c][n][d]
__device__ float g_hinit[B_SZ * NC * NSTATE * DMODEL];
__device__ float g_dtsum[B_SZ * NC * DMODEL];

__device__ __forceinline__ float softplus_f(float z) {
    return (z > 20.0f) ? z : log1pf(expf(z));
}

// ---------------- TF32 tensor-core GEMM: delta = softplus(x @ Wd + bd) -------
#define BM 128
#define BN 128
#define BKT 16
#define ASTR 20
#define BSTR 136

__device__ __forceinline__ void cp_async16(void* smem, const void* gmem) {
    uint32_t s = (uint32_t)__cvta_generic_to_shared(smem);
    asm volatile("cp.async.cg.shared.global [%0], [%1], 16;\n" :: "r"(s), "l"(gmem));
}
__device__ __forceinline__ uint32_t to_tf32(float f) {
    uint32_t u;
    asm volatile("cvt.rna.tf32.f32 %0, %1;\n" : "=r"(u) : "f"(f));
    return u;
}

__global__ __launch_bounds__(256, 2)
void gemm_delta_tf32_kernel(const float* __restrict__ X,
                            const float* __restrict__ W,
                            const float* __restrict__ bias) {
    __shared__ float As[2][BM * ASTR];
    __shared__ float Bs[2][BKT * BSTR];

    const int bm = blockIdx.y * BM;
    const int bn = blockIdx.x * BN;
    const int tid = threadIdx.x;
    const int lane = tid & 31;
    const int w = tid >> 5;
    const int g = lane >> 2;
    const int t = lane & 3;
    const int warpM = w >> 1;
    const int warpN = w & 1;
    const int mrow0 = warpM * 32;
    const int ncol0 = warpN * 64;

    float acc[2][8][4];
    #pragma unroll
    for (int i = 0; i < 2; i++)
        #pragma unroll
        for (int j = 0; j < 8; j++)
            #pragma unroll
            for (int q = 0; q < 4; q++) acc[i][j][q] = 0.0f;

    const int NIT = DMODEL / BKT;

    auto issue_tile = [&](int it, int buf) {
        int k0 = it * BKT;
        #pragma unroll
        for (int i = 0; i < 2; i++) {
            int idx = tid + i * 256;
            int row = idx >> 2;
            int kk  = (idx & 3) * 4;
            cp_async16(&As[buf][row * ASTR + kk],
                       &X[(size_t)(bm + row) * DMODEL + k0 + kk]);
            int krow = idx >> 5;
            int col  = (idx & 31) * 4;
            cp_async16(&Bs[buf][krow * BSTR + col],
                       &W[(size_t)(k0 + krow) * DMODEL + bn + col]);
        }
        asm volatile("cp.async.commit_group;\n");
    };

    issue_tile(0, 0);

    for (int it = 0; it < NIT; it++) {
        const int p = it & 1;
        if (it + 1 < NIT) issue_tile(it + 1, p ^ 1);
        if (it + 1 < NIT) { asm volatile("cp.async.wait_group 1;\n"); }
        else              { asm volatile("cp.async.wait_group 0;\n"); }
        __syncthreads();

        #pragma unroll
        for (int ks = 0; ks < 2; ks++) {
            const int k = ks * 8;
            uint32_t af[2][4];
            #pragma unroll
            for (int mt = 0; mt < 2; mt++) {
                int r0 = mrow0 + mt * 16;
                af[mt][0] = to_tf32(As[p][(r0 + g)     * ASTR + k + t]);
                af[mt][1] = to_tf32(As[p][(r0 + 8 + g) * ASTR + k + t]);
                af[mt][2] = to_tf32(As[p][(r0 + g)     * ASTR + k + t + 4]);
                af[mt][3] = to_tf32(As[p][(r0 + 8 + g) * ASTR + k + t + 4]);
            }
            uint32_t bf[8][2];
            #pragma unroll
            for (int nt = 0; nt < 8; nt++) {
                int c0 = ncol0 + nt * 8 + g;
                bf[nt][0] = to_tf32(Bs[p][(k + t)     * BSTR + c0]);
                bf[nt][1] = to_tf32(Bs[p][(k + t + 4) * BSTR + c0]);
            }
            #pragma unroll
            for (int mt = 0; mt < 2; mt++)
                #pragma unroll
                for (int nt = 0; nt < 8; nt++) {
                    asm volatile(
                        "mma.sync.aligned.m16n8k8.row.col.f32.tf32.tf32.f32 "
                        "{%0,%1,%2,%3}, {%4,%5,%6,%7}, {%8,%9}, {%0,%1,%2,%3};\n"
                        : "+f"(acc[mt][nt][0]), "+f"(acc[mt][nt][1]),
                          "+f"(acc[mt][nt][2]), "+f"(acc[mt][nt][3])
                        : "r"(af[mt][0]), "r"(af[mt][1]), "r"(af[mt][2]), "r"(af[mt][3]),
                          "r"(bf[nt][0]), "r"(bf[nt][1]));
                }
        }
        __syncthreads();
    }

    #pragma unroll
    for (int nt = 0; nt < 8; nt++) {
        int col = bn + ncol0 + nt * 8 + 2 * t;
        float b0 = bias[col];
        float b1 = bias[col + 1];
        #pragma unroll
        for (int mt = 0; mt < 2; mt++) {
            int r0 = bm + mrow0 + mt * 16 + g;
            float2 v0, v1;
            v0.x = softplus_f(acc[mt][nt][0] + b0);
            v0.y = softplus_f(acc[mt][nt][1] + b1);
            v1.x = softplus_f(acc[mt][nt][2] + b0);
            v1.y = softplus_f(acc[mt][nt][3] + b1);
            *(float2*)&g_delta[(size_t)r0 * DMODEL + col] = v0;
            *(float2*)&g_delta[(size_t)(r0 + 8) * DMODEL + col] = v1;
        }
    }
}

// ---------------- Kernel 2: Bm/Cm projections --------------------------------
__global__ __launch_bounds__(256)
void proj_bc_kernel(const float* __restrict__ x,
                    const float* __restrict__ Wb, const float* __restrict__ bb,
                    const float* __restrict__ Wc, const float* __restrict__ bc) {
    const int warp = threadIdx.x >> 5;
    const int lane = threadIdx.x & 31;
    const int row0 = (blockIdx.x * 8 + warp) * 4;
    const int j = lane & 15;
    const bool isC = lane >= 16;
    const float* __restrict__ W = isC ? Wc : Wb;

    float acc0 = 0.f, acc1 = 0.f, acc2 = 0.f, acc3 = 0.f;
    for (int k0 = 0; k0 < DMODEL; k0 += 32) {
        float x0 = x[(row0 + 0) * DMODEL + k0 + lane];
        float x1 = x[(row0 + 1) * DMODEL + k0 + lane];
        float x2 = x[(row0 + 2) * DMODEL + k0 + lane];
        float x3 = x[(row0 + 3) * DMODEL + k0 + lane];
        #pragma unroll
        for (int kk = 0; kk < 32; kk++) {
            float w = W[(k0 + kk) * NSTATE + j];
            acc0 = fmaf(__shfl_sync(0xffffffffu, x0, kk), w, acc0);
            acc1 = fmaf(__shfl_sync(0xffffffffu, x1, kk), w, acc1);
            acc2 = fmaf(__shfl_sync(0xffffffffu, x2, kk), w, acc2);
            acc3 = fmaf(__shfl_sync(0xffffffffu, x3, kk), w, acc3);
        }
    }
    float bias = isC ? bc[j] : bb[j];
    float* out = isC ? g_Cm : g_Bm;
    out[(row0 + 0) * NSTATE + j] = acc0 + bias;
    out[(row0 + 1) * NSTATE + j] = acc1 + bias;
    out[(row0 + 2) * NSTATE + j] = acc2 + bias;
    out[(row0 + 3) * NSTATE + j] = acc3 + bias;
}

// ---------------- A_log smem staging helper ----------------------------------
// Loads A[n] = -exp(A_log[d,n]) for the block's 256 d-channels, coalesced.
__device__ __forceinline__ void load_A_row(float* sA, const float* __restrict__ A_log,
                                           int d0, float A[NSTATE]) {
    const float4* src = (const float4*)(A_log + (size_t)d0 * NSTATE);
    float4* dst = (float4*)sA;
    for (int i = threadIdx.x; i < 256 * NSTATE / 4; i += 256)
        dst[i] = src[i];
    __syncthreads();
    #pragma unroll
    for (int n = 0; n < NSTATE; n++)
        A[n] = -__expf(sA[threadIdx.x * NSTATE + n]);
}

// ---------------- Kernel 3: scan pass 1 --------------------------------------
__global__ __launch_bounds__(256)
void scan_pass1_kernel(const float* __restrict__ x,
                       const float* __restrict__ A_log) {
    const int d = blockIdx.x * 256 + threadIdx.x;
    const int c = blockIdx.y;
    const int b = blockIdx.z;
    const int t0 = c * CHUNK;

    __shared__ float sB[CHUNK * NSTATE];
    __shared__ float sA[256 * NSTATE];
    for (int i = threadIdx.x; i < CHUNK * NSTATE; i += 256)
        sB[i] = g_Bm[(b * SEQ + t0) * NSTATE + i];

    float A[NSTATE];
    load_A_row(sA, A_log, blockIdx.x * 256, A);   // includes __syncthreads

    float h[NSTATE];
    #pragma unroll
    for (int n = 0; n < NSTATE; n++) h[n] = 0.0f;
    float dts = 0.0f;

    const float* __restrict__ xp = x       + (size_t)(b * SEQ + t0) * DMODEL + d;
    const float* __restrict__ dp = g_delta + (size_t)(b * SEQ + t0) * DMODEL + d;
    const float4* sB4 = (const float4*)sB;

    #pragma unroll 4
    for (int t = 0; t < CHUNK; t++) {
        float xv = xp[t * DMODEL];
        float dt = dp[t * DMODEL];
        dts += dt;
        float dtx = dt * xv;
        float4 q0 = sB4[t * 4 + 0];
        float4 q1 = sB4[t * 4 + 1];
        float4 q2 = sB4[t * 4 + 2];
        float4 q3 = sB4[t * 4 + 3];
        const float bb[16] = {q0.x,q0.y,q0.z,q0.w, q1.x,q1.y,q1.z,q1.w,
                              q2.x,q2.y,q2.z,q2.w, q3.x,q3.y,q3.z,q3.w};
        #pragma unroll
        for (int n = 0; n < NSTATE; n++) {
            float ab = __expf(dt * A[n]);
            h[n] = fmaf(ab, h[n], dtx * bb[n]);
        }
    }

    const int base = ((b * NC + c) * NSTATE) * DMODEL + d;
    #pragma unroll
    for (int n = 0; n < NSTATE; n++)
        g_hfin[base + n * DMODEL] = h[n];
    g_dtsum[(b * NC + c) * DMODEL + d] = dts;
}

// ---------------- Kernel 4: chunk combine (pipelined register prefetch) ------
#define PF 8
__global__ __launch_bounds__(256)
void combine_kernel(const float* __restrict__ A_log) {
    const int d = blockIdx.x * 256 + threadIdx.x;
    const int n = blockIdx.y;
    const int b = blockIdx.z;

    const float A = -__expf(A_log[d * NSTATE + n]);

    const int cstride = NSTATE * DMODEL;                       // step per chunk in hfin
    const float* __restrict__ hfp = g_hfin  + ((size_t)(b * NC) * NSTATE + n) * DMODEL + d;
    float* __restrict__ hip       = g_hinit + ((size_t)(b * NC) * NSTATE + n) * DMODEL + d;
    const float* __restrict__ dsp = g_dtsum + (size_t)(b * NC) * DMODEL + d;

    float dtsA[PF], hfA[PF], dtsB[PF], hfB[PF];
    #pragma unroll
    for (int i = 0; i < PF; i++) {
        dtsA[i] = dsp[i * DMODEL];
        hfA[i]  = hfp[i * cstride];
    }

    float h = 0.0f;
    #pragma unroll
    for (int c0 = 0; c0 < NC; c0 += PF) {
        const bool more = (c0 + PF < NC);
        // prefetch next group (B) before consuming current (A)
        if (more) {
            #pragma unroll
            for (int i = 0; i < PF; i++) {
                dtsB[i] = dsp[(c0 + PF + i) * DMODEL];
                hfB[i]  = hfp[(size_t)(c0 + PF + i) * cstride];
            }
        }
        #pragma unroll
        for (int i = 0; i < PF; i++) {
            hip[(size_t)(c0 + i) * cstride] = h;
            h = fmaf(__expf(dtsA[i] * A), h, hfA[i]);
        }
        #pragma unroll
        for (int i = 0; i < PF; i++) { dtsA[i] = dtsB[i]; hfA[i] = hfB[i]; }
    }
}

// ---------------- Kernel 5: scan pass 2 --------------------------------------
__global__ __launch_bounds__(256)
void scan_pass2_kernel(const float* __restrict__ x,
                       const float* __restrict__ A_log,
                       const float* __restrict__ D_skip,
                       float* __restrict__ y) {
    const int d = blockIdx.x * 256 + threadIdx.x;
    const int c = blockIdx.y;
    const int b = blockIdx.z;
    const int t0 = c * CHUNK;

    __shared__ float sB[CHUNK * NSTATE];
    __shared__ float sC[CHUNK * NSTATE];
    __shared__ float sA[256 * NSTATE];
    for (int i = threadIdx.x; i < CHUNK * NSTATE; i += 256) {
        sB[i] = g_Bm[(b * SEQ + t0) * NSTATE + i];
        sC[i] = g_Cm[(b * SEQ + t0) * NSTATE + i];
    }

    float A[NSTATE];
    load_A_row(sA, A_log, blockIdx.x * 256, A);   // includes __syncthreads

    float h[NSTATE];
    const int base = ((b * NC + c) * NSTATE) * DMODEL + d;
    #pragma unroll
    for (int n = 0; n < NSTATE; n++)
        h[n] = g_hinit[base + n * DMODEL];

    const float dsk = D_skip[d];
    const float* __restrict__ xp = x       + (size_t)(b * SEQ + t0) * DMODEL + d;
    const float* __restrict__ dp = g_delta + (size_t)(b * SEQ + t0) * DMODEL + d;
    float* __restrict__ yp       = y       + (size_t)(b * SEQ + t0) * DMODEL + d;
    const float4* sB4 = (const float4*)sB;
    const float4* sC4 = (const float4*)sC;

    #pragma unroll 4
    for (int t = 0; t < CHUNK; t++) {
        float xv = xp[t * DMODEL];
        float dt = dp[t * DMODEL];
        float dtx = dt * xv;
        float acc = xv * dsk;
        float4 q0 = sB4[t * 4 + 0];
        float4 q1 = sB4[t * 4 + 1];
        float4 q2 = sB4[t * 4 + 2];
        float4 q3 = sB4[t * 4 + 3];
        const float bb[16] = {q0.x,q0.y,q0.z,q0.w, q1.x,q1.y,q1.z,q1.w,
                              q2.x,q2.y,q2.z,q2.w, q3.x,q3.y,q3.z,q3.w};
        float4 r0 = sC4[t * 4 + 0];
        float4 r1 = sC4[t * 4 + 1];
        float4 r2 = sC4[t * 4 + 2];
        float4 r3 = sC4[t * 4 + 3];
        const float cc[16] = {r0.x,r0.y,r0.z,r0.w, r1.x,r1.y,r1.z,r1.w,
                              r2.x,r2.y,r2.z,r2.w, r3.x,r3.y,r3.z,r3.w};
        #pragma unroll
        for (int n = 0; n < NSTATE; n++) {
            float ab = __expf(dt * A[n]);
            h[n] = fmaf(ab, h[n], dtx * bb[n]);
            acc = fmaf(h[n], cc[n], acc);
        }
        yp[t * DMODEL] = acc;
    }
}

// ---------------- launch ----------------
extern "C" void kernel_launch(void* const* d_in, const int* in_sizes, int n_in,
                              void* d_out, int out_size) {
    const float* x      = (const float*)d_in[0];
    const float* A_log  = (const float*)d_in[1];
    const float* D_skip = (const float*)d_in[2];
    const float* Wd     = (const float*)d_in[3];
    const float* bd     = (const float*)d_in[4];
    const float* Wb     = (const float*)d_in[5];
    const float* bb     = (const float*)d_in[6];
    const float* Wc     = (const float*)d_in[7];
    const float* bc     = (const float*)d_in[8];
    float* y = (float*)d_out;

    dim3 ggrid(DMODEL / BN, MROWS / BM);          // (8, 64)
    gemm_delta_tf32_kernel<<<ggrid, 256>>>(x, Wd, bd);

    proj_bc_kernel<<<MROWS / 32, 256>>>(x, Wb, bb, Wc, bc);

    dim3 sgrid(DMODEL / 256, NC, B_SZ);           // (4, 64, 4) = 1024 blocks
    scan_pass1_kernel<<<sgrid, 256>>>(x, A_log);
    dim3 cgrid(DMODEL / 256, NSTATE, B_SZ);       // 256 blocks
    combine_kernel<<<cgrid, 256>>>(A_log);
    scan_pass2_kernel<<<sgrid, 256>>>(x, A_log, D_skip, y);
}